// round 6
// baseline (speedup 1.0000x reference)
#include <cuda_runtime.h>
#include <cuda_bf16.h>
#include <cstdint>

// ---------------------------------------------------------------------------
// y[m, n*410+f] = u[m,f] + sx[m,n]*G[n,f] + c[f]
//   U[:, 0:410] = X @ Wfc^T,  U[:, 410:420] = X @ Wsel^T  (one tf32 GEMM)
//   G = Wfc @ Wexp, c = Wfc @ bexp + bfc
// GEMM: mma.sync m16n8k8 tf32, cp.async 4-stage ring, ldmatrix.
// 256 thr / 8 warps: K-SPLIT warp specialization — group 0 handles k[0:16),
// group 1 k[16:32) of each BK=32 tile; each group tiles 2x2 of 64x56.
// 2 warps/SMSP for latency hiding at minimum (A x2 / B x2) duplication.
// ---------------------------------------------------------------------------

#define KDIM    4096
#define NFC     410
#define NCOLS   420
#define USTRIDE 432
#define MMAX    4096

#define BM 128
#define BN 112
#define BK 32
#define NKT (KDIM / BK)              // 128
#define STAGES 4
#define TILE_A  (BM * BK * 4)        // 16384
#define TILE_B  (BN * BK * 4)        // 14336
#define STAGE_BYTES (TILE_A + TILE_B) // 30720

#define KSPLIT 8
#define PREPW  4576

__device__ float g_U[MMAX * USTRIDE];
__device__ float g_G[10 * 416];
__device__ float g_c[416];
__device__ float g_part[KSPLIT][PREPW];

// ---------------- helpers ----------------------------------------------------
__device__ __forceinline__ uint32_t smem_u32(const void* p) {
    uint32_t a;
    asm("{ .reg .u64 t; cvta.to.shared.u64 t, %1; cvt.u32.u64 %0, t; }" : "=r"(a) : "l"(p));
    return a;
}
__device__ __forceinline__ void cp16(uint32_t dst, const void* src, uint32_t srcsize) {
    asm volatile("cp.async.cg.shared.global [%0], [%1], 16, %2;"
                 :: "r"(dst), "l"(src), "r"(srcsize) : "memory");
}
__device__ __forceinline__ void cp_commit() {
    asm volatile("cp.async.commit_group;" ::: "memory");
}
__device__ __forceinline__ void cp_wait2() {
    asm volatile("cp.async.wait_group 2;" ::: "memory");
}
__device__ __forceinline__ void ldsm4(uint32_t* r, uint32_t a) {
    asm volatile("ldmatrix.sync.aligned.m8n8.x4.shared.b16 {%0,%1,%2,%3}, [%4];"
                 : "=r"(r[0]), "=r"(r[1]), "=r"(r[2]), "=r"(r[3]) : "r"(a));
}
__device__ __forceinline__ void ldsm2(uint32_t* r, uint32_t a) {
    asm volatile("ldmatrix.sync.aligned.m8n8.x2.shared.b16 {%0,%1}, [%2];"
                 : "=r"(r[0]), "=r"(r[1]) : "r"(a));
}
__device__ __forceinline__ uint32_t f2tf(uint32_t v) {
    uint32_t r;
    asm("cvt.rna.tf32.f32 %0, %1;" : "=r"(r) : "f"(__uint_as_float(v)));
    return r;
}
__device__ __forceinline__ void mma8(float* c, const uint32_t* a, const uint32_t* b) {
    asm volatile(
        "mma.sync.aligned.m16n8k8.row.col.f32.tf32.tf32.f32 "
        "{%0,%1,%2,%3}, {%4,%5,%6,%7}, {%8,%9}, {%0,%1,%2,%3};"
        : "+f"(c[0]), "+f"(c[1]), "+f"(c[2]), "+f"(c[3])
        : "r"(a[0]), "r"(a[1]), "r"(a[2]), "r"(a[3]), "r"(b[0]), "r"(b[1]));
}

// ---------------------------------------------------------------------------
// prep pass 1 + 2 (unchanged from r5 — fast k-split reduction)
// ---------------------------------------------------------------------------
__global__ void prep_part(const float* __restrict__ Wfc, const float* __restrict__ Wexp,
                          const float* __restrict__ bexp) {
    int f  = blockIdx.x;
    int kz = blockIdx.y;
    int k0 = kz * 512;
    const float* wrow = Wfc + (size_t)f * KDIM + k0;
    float acc[11];
#pragma unroll
    for (int v = 0; v < 11; v++) acc[v] = 0.f;
#pragma unroll
    for (int it = 0; it < 4; it++) {
        int k = it * 128 + threadIdx.x;
        float w = wrow[k];
        const float* we = Wexp + (size_t)(k0 + k) * 10;
#pragma unroll
        for (int n = 0; n < 10; n++) acc[n] += w * we[n];
        acc[10] += w * bexp[k0 + k];
    }
    __shared__ float red[4][11];
    int lane = threadIdx.x & 31, warp = threadIdx.x >> 5;
#pragma unroll
    for (int v = 0; v < 11; v++) {
        float s = acc[v];
#pragma unroll
        for (int o = 16; o; o >>= 1) s += __shfl_xor_sync(0xffffffffu, s, o);
        if (lane == 0) red[warp][v] = s;
    }
    __syncthreads();
    if (threadIdx.x < 11) {
        float s = red[0][threadIdx.x] + red[1][threadIdx.x] +
                  red[2][threadIdx.x] + red[3][threadIdx.x];
        g_part[kz][threadIdx.x * 416 + f] = s;
    }
}

__global__ void prep_combine(const float* __restrict__ bfc) {
    int i = blockIdx.x * 256 + threadIdx.x;
    if (i >= PREPW) return;
    float s = 0.f;
#pragma unroll
    for (int kz = 0; kz < KSPLIT; kz++) s += g_part[kz][i];
    if (i < 10 * 416) {
        g_G[i] = s;
    } else {
        int f = i - 10 * 416;
        g_c[f] = (f < NFC) ? s + bfc[f] : s;
    }
}

// ---------------------------------------------------------------------------
// GEMM: 128x112 block, 256 thr, 8 warps = 2 k-groups x (2x2 of 64x56)
// ---------------------------------------------------------------------------
__global__ __launch_bounds__(256, 1)
void gemm_kernel(const float* __restrict__ x, const float* __restrict__ Wfc,
                 const float* __restrict__ Wsel) {
    extern __shared__ char dyn[];
    char* bufs = (char*)(((uintptr_t)dyn + 1023) & ~(uintptr_t)1023);
    const uint32_t bufs_u32 = smem_u32(bufs);

    const int tid  = threadIdx.x;
    const int lane = tid & 31;
    const int warp = tid >> 5;
    const int g    = warp >> 2;        // k-group 0/1
    const int w2   = warp & 3;
    const int wm   = w2 >> 1;          // 0..1
    const int wn   = w2 & 1;           // 0..1
    const int m0   = blockIdx.y * BM;
    const int n0   = blockIdx.x * BN;

    // ---- loader: row = tid>>1 (A: 0..127, B: 0..111), 4 chunks each ----
    const int lrow = tid >> 1;
    const int lc0  = (tid & 1) * 4;
    uint32_t adst[4];
#pragma unroll
    for (int i = 0; i < 4; i++)
        adst[i] = (uint32_t)(lrow * 128 + (((lc0 + i) * 16) ^ ((lrow & 7) << 4)));

    const char* aglob = (const char*)(x + (size_t)(m0 + lrow) * KDIM + lc0 * 4);
    const bool bvalid = (tid < 224);
    const char* bglob = (const char*)Wfc;
    uint32_t    bszv  = 0;
    if (bvalid) {
        int bc = n0 + lrow;
        if (bc < NFC)        { bglob = (const char*)(Wfc  + (size_t)bc * KDIM + lc0 * 4); bszv = 16; }
        else if (bc < NCOLS) { bglob = (const char*)(Wsel + (size_t)(bc - NFC) * KDIM + lc0 * 4); bszv = 16; }
    }

    auto issue = [&](int kt) {
        int stage = kt & (STAGES - 1);
        uint32_t sb = bufs_u32 + stage * STAGE_BYTES;
        const char* as = aglob + (size_t)kt * 128;
#pragma unroll
        for (int i = 0; i < 4; i++) cp16(sb + adst[i], as + i * 16, 16);
        if (bvalid) {
            const char* bs = bglob + (size_t)kt * 128;
#pragma unroll
            for (int i = 0; i < 4; i++) cp16(sb + TILE_A + adst[i], bs + i * 16, bszv);
        }
    };

    // ---- fragment constants ----
    const uint32_t aoff  = (uint32_t)((wm * 64 + (lane & 15)) * 128);
    const uint32_t xS    = (uint32_t)((lane & 7) << 4);
    const uint32_t hA    = (lane & 16) ? 16u : 0u;
    const uint32_t boffp = (uint32_t)((wn * 56 + (lane & 7) + ((lane & 16) ? 8 : 0)) * 128);
    const uint32_t boff2 = (uint32_t)((wn * 56 + 48 + (lane & 7)) * 128);
    const uint32_t hB    = (lane & 8) ? 16u : 0u;
    const uint32_t kbase = (uint32_t)(g * 64);   // byte offset of this group's k-half

    float acc[4][7][4];
#pragma unroll
    for (int mi = 0; mi < 4; mi++)
#pragma unroll
        for (int nj = 0; nj < 7; nj++)
#pragma unroll
            for (int q = 0; q < 4; q++) acc[mi][nj][q] = 0.f;

    issue(0); cp_commit();
    issue(1); cp_commit();
    issue(2); cp_commit();

#pragma unroll 1
    for (int kt = 0; kt < NKT; kt++) {
        cp_wait2();
        __syncthreads();
        if (kt + 3 < NKT) issue(kt + 3);
        cp_commit();

        const uint32_t As = bufs_u32 + (kt & (STAGES - 1)) * STAGE_BYTES;
        const uint32_t Bs = As + TILE_A;
#pragma unroll
        for (int s = 0; s < 2; s++) {
            const uint32_t kb = kbase + s * 32;
            const uint32_t ka_ = (kb + hA) ^ xS;
            const uint32_t kb_ = (kb + hB) ^ xS;
            uint32_t a[4][4], bp[3][4], b6[2];
#pragma unroll
            for (int mi = 0; mi < 4; mi++) ldsm4(a[mi], As + aoff + mi * 2048 + ka_);
#pragma unroll
            for (int p = 0; p < 3; p++)   ldsm4(bp[p], Bs + boffp + p * 2048 + kb_);
            ldsm2(b6, Bs + boff2 + kb_);
#pragma unroll
            for (int mi = 0; mi < 4; mi++)
#pragma unroll
                for (int q = 0; q < 4; q++) a[mi][q] = f2tf(a[mi][q]);
#pragma unroll
            for (int p = 0; p < 3; p++)
#pragma unroll
                for (int q = 0; q < 4; q++) bp[p][q] = f2tf(bp[p][q]);
            b6[0] = f2tf(b6[0]); b6[1] = f2tf(b6[1]);
#pragma unroll
            for (int mi = 0; mi < 4; mi++) {
#pragma unroll
                for (int p = 0; p < 3; p++) {
                    mma8(acc[mi][2 * p],     a[mi], &bp[p][0]);
                    mma8(acc[mi][2 * p + 1], a[mi], &bp[p][2]);
                }
                mma8(acc[mi][6], a[mi], b6);
            }
        }
    }

    // ---- merge group 1 partials into group 0 via smem ----
    __syncthreads();
    float* ms = reinterpret_cast<float*>(bufs);   // 128 x 113 floats
    const int tslot = w2 * 32 + lane;
    if (g == 1) {
#pragma unroll
        for (int mi = 0; mi < 4; mi++)
#pragma unroll
            for (int nj = 0; nj < 7; nj++)
#pragma unroll
                for (int q = 0; q < 4; q++)
                    ms[tslot * 113 + mi * 28 + nj * 4 + q] = acc[mi][nj][q];
    }
    __syncthreads();
    if (g == 0) {
#pragma unroll
        for (int mi = 0; mi < 4; mi++)
#pragma unroll
            for (int nj = 0; nj < 7; nj++)
#pragma unroll
                for (int q = 0; q < 4; q++)
                    acc[mi][nj][q] += ms[tslot * 113 + mi * 28 + nj * 4 + q];

        // ---- write U (guard pad columns) ----
        const int gid = lane >> 2;
        const int tig = lane & 3;
#pragma unroll
        for (int mi = 0; mi < 4; mi++) {
            int r0 = m0 + wm * 64 + mi * 16 + gid;
#pragma unroll
            for (int nj = 0; nj < 7; nj++) {
                int col = n0 + wn * 56 + nj * 8 + 2 * tig;
                if (col < NCOLS) {
                    *reinterpret_cast<float2*>(&g_U[(size_t)r0 * USTRIDE + col]) =
                        make_float2(acc[mi][nj][0], acc[mi][nj][1]);
                    *reinterpret_cast<float2*>(&g_U[(size_t)(r0 + 8) * USTRIDE + col]) =
                        make_float2(acc[mi][nj][2], acc[mi][nj][3]);
                }
            }
        }
    }
}

// ---------------------------------------------------------------------------
// epilogue: 2 rows per block, float4 loads, float4/float2 stores
// ---------------------------------------------------------------------------
__global__ void epi_kernel(const float* __restrict__ bsel, float* __restrict__ out) {
    int m = blockIdx.x * 2 + (threadIdx.x >> 7);
    int ht = threadIdx.x & 127;
    __shared__ float sx[2][10];
    if (ht < 10)
        sx[threadIdx.x >> 7][ht] =
            g_U[(size_t)m * USTRIDE + NFC + ht] + bsel[ht];
    __syncthreads();
    const float* Ur = g_U + (size_t)m * USTRIDE;
    float* orow = out + (size_t)m * 4096;
#pragma unroll 1
    for (int n = 0; n < 10; n++) {
        int base = n * NFC;
        float sxn = sx[threadIdx.x >> 7][n];
        int lim = (n == 9) ? (4096 - base) : NFC;   // 410 or 406
        int body = lim & ~3;
        const float* Gn = g_G + n * 416;
        for (int f = ht * 4; f < body; f += 512) {
            float4 u = *reinterpret_cast<const float4*>(Ur + f);
            float4 gg = *reinterpret_cast<const float4*>(Gn + f);
            float4 cc = *reinterpret_cast<const float4*>(g_c + f);
            float4 r;
            r.x = fmaf(sxn, gg.x, u.x + cc.x);
            r.y = fmaf(sxn, gg.y, u.y + cc.y);
            r.z = fmaf(sxn, gg.z, u.z + cc.z);
            r.w = fmaf(sxn, gg.w, u.w + cc.w);
            if (base & 2) {
                *reinterpret_cast<float2*>(orow + base + f)     = make_float2(r.x, r.y);
                *reinterpret_cast<float2*>(orow + base + f + 2) = make_float2(r.z, r.w);
            } else {
                *reinterpret_cast<float4*>(orow + base + f) = r;
            }
        }
        if (ht < lim - body) {
            int f = body + ht;
            orow[base + f] = fmaf(sxn, Gn[f], Ur[f] + g_c[f]);
        }
    }
}

// ---------------------------------------------------------------------------
extern "C" void kernel_launch(void* const* d_in, const int* in_sizes, int n_in,
                              void* d_out, int out_size) {
    const float* x    = (const float*)d_in[0];
    const float* Wsel = (const float*)d_in[1];
    const float* bsel = (const float*)d_in[2];
    const float* Wexp = (const float*)d_in[3];
    const float* bexp = (const float*)d_in[4];
    const float* Wfc  = (const float*)d_in[5];
    const float* bfc  = (const float*)d_in[6];
    float* out = (float*)d_out;

    int M = in_sizes[0] / KDIM;   // 4096

    const int smem_bytes = STAGES * STAGE_BYTES + 1024;   // 123904
    cudaFuncSetAttribute(gemm_kernel, cudaFuncAttributeMaxDynamicSharedMemorySize, smem_bytes);

    prep_part<<<dim3(NFC, KSPLIT), 128>>>(Wfc, Wexp, bexp);
    prep_combine<<<(PREPW + 255) / 256, 256>>>(bfc);
    dim3 grid(4, M / BM);   // 4 x 32 = 128 blocks
    gemm_kernel<<<grid, 256, smem_bytes>>>(x, Wfc, Wsel);
    epi_kernel<<<M / 2, 256>>>(bsel, out);
}

// round 7
// speedup vs baseline: 1.2526x; 1.2526x over previous
#include <cuda_runtime.h>
#include <cstdint>

// ---------------------------------------------------------------------------
// y[m, n*410+f] = u[m,f] + sx[m,n]*G[n,f] + c[f]
//   U[:, 0:410] = X @ Wfc^T,  U[:, 410:420] = X @ Wsel^T  (one tf32 GEMM)
//   G = Wfc @ Wexp, c = Wfc @ bexp + bfc
// GEMM: r5 shape (128 thr, 4 warps of 32x112, BN=112, cp.async 4-stage ring)
// + intra-warp FRAGMENT DOUBLE-BUFFERING: ldsm(ks+1) issued under the mma
// burst of ks, cvt(ks+1) after — hides the ldsm->cvt->mma chain that made
// r5 latency-bound at 1 warp/SMSP.
// ---------------------------------------------------------------------------

#define KDIM    4096
#define NFC     410
#define NCOLS   420
#define USTRIDE 432
#define MMAX    4096

#define BM 128
#define BN 112
#define BK 32
#define NKT (KDIM / BK)              // 128
#define STAGES 4
#define TILE_A  (BM * BK * 4)        // 16384
#define TILE_B  (BN * BK * 4)        // 14336
#define STAGE_BYTES (TILE_A + TILE_B) // 30720

#define KSPLIT 8
#define PREPW  4576

__device__ float g_U[MMAX * USTRIDE];
__device__ float g_G[10 * 416];
__device__ float g_c[416];
__device__ float g_part[KSPLIT][PREPW];

// ---------------- helpers ----------------------------------------------------
__device__ __forceinline__ uint32_t smem_u32(const void* p) {
    uint32_t a;
    asm("{ .reg .u64 t; cvta.to.shared.u64 t, %1; cvt.u32.u64 %0, t; }" : "=r"(a) : "l"(p));
    return a;
}
__device__ __forceinline__ void cp16(uint32_t dst, const void* src, uint32_t srcsize) {
    asm volatile("cp.async.cg.shared.global [%0], [%1], 16, %2;"
                 :: "r"(dst), "l"(src), "r"(srcsize) : "memory");
}
__device__ __forceinline__ void cp_commit() {
    asm volatile("cp.async.commit_group;" ::: "memory");
}
__device__ __forceinline__ void cp_wait2() {
    asm volatile("cp.async.wait_group 2;" ::: "memory");
}
__device__ __forceinline__ void ldsm4(uint32_t* r, uint32_t a) {
    asm volatile("ldmatrix.sync.aligned.m8n8.x4.shared.b16 {%0,%1,%2,%3}, [%4];"
                 : "=r"(r[0]), "=r"(r[1]), "=r"(r[2]), "=r"(r[3]) : "r"(a));
}
__device__ __forceinline__ uint32_t f2tf(uint32_t v) {
    uint32_t r;
    asm("cvt.rna.tf32.f32 %0, %1;" : "=r"(r) : "f"(__uint_as_float(v)));
    return r;
}
__device__ __forceinline__ void mma8(float* c, const uint32_t* a, const uint32_t* b) {
    asm volatile(
        "mma.sync.aligned.m16n8k8.row.col.f32.tf32.tf32.f32 "
        "{%0,%1,%2,%3}, {%4,%5,%6,%7}, {%8,%9}, {%0,%1,%2,%3};"
        : "+f"(c[0]), "+f"(c[1]), "+f"(c[2]), "+f"(c[3])
        : "r"(a[0]), "r"(a[1]), "r"(a[2]), "r"(a[3]), "r"(b[0]), "r"(b[1]));
}

// ---------------------------------------------------------------------------
// prep pass 1 + 2 (k-split reduction, unchanged)
// ---------------------------------------------------------------------------
__global__ void prep_part(const float* __restrict__ Wfc, const float* __restrict__ Wexp,
                          const float* __restrict__ bexp) {
    int f  = blockIdx.x;
    int kz = blockIdx.y;
    int k0 = kz * 512;
    const float* wrow = Wfc + (size_t)f * KDIM + k0;
    float acc[11];
#pragma unroll
    for (int v = 0; v < 11; v++) acc[v] = 0.f;
#pragma unroll
    for (int it = 0; it < 4; it++) {
        int k = it * 128 + threadIdx.x;
        float w = wrow[k];
        const float* we = Wexp + (size_t)(k0 + k) * 10;
#pragma unroll
        for (int n = 0; n < 10; n++) acc[n] += w * we[n];
        acc[10] += w * bexp[k0 + k];
    }
    __shared__ float red[4][11];
    int lane = threadIdx.x & 31, warp = threadIdx.x >> 5;
#pragma unroll
    for (int v = 0; v < 11; v++) {
        float s = acc[v];
#pragma unroll
        for (int o = 16; o; o >>= 1) s += __shfl_xor_sync(0xffffffffu, s, o);
        if (lane == 0) red[warp][v] = s;
    }
    __syncthreads();
    if (threadIdx.x < 11) {
        float s = red[0][threadIdx.x] + red[1][threadIdx.x] +
                  red[2][threadIdx.x] + red[3][threadIdx.x];
        g_part[kz][threadIdx.x * 416 + f] = s;
    }
}

__global__ void prep_combine(const float* __restrict__ bfc) {
    int i = blockIdx.x * 256 + threadIdx.x;
    if (i >= PREPW) return;
    float s = 0.f;
#pragma unroll
    for (int kz = 0; kz < KSPLIT; kz++) s += g_part[kz][i];
    if (i < 10 * 416) {
        g_G[i] = s;
    } else {
        int f = i - 10 * 416;
        g_c[f] = (f < NFC) ? s + bfc[f] : s;
    }
}

// ---------------------------------------------------------------------------
// GEMM: 128x112 block, 4 warps (4wm x 1wn) of 32x112, fragment double-buffer
// ---------------------------------------------------------------------------
__global__ __launch_bounds__(128, 1)
void gemm_kernel(const float* __restrict__ x, const float* __restrict__ Wfc,
                 const float* __restrict__ Wsel) {
    extern __shared__ char dyn[];
    char* bufs = (char*)(((uintptr_t)dyn + 1023) & ~(uintptr_t)1023);
    const uint32_t bufs_u32 = smem_u32(bufs);

    const int tid  = threadIdx.x;
    const int lane = tid & 31;
    const int warp = tid >> 5;         // wm 0..3, single wn
    const int m0   = blockIdx.y * BM;
    const int n0   = blockIdx.x * BN;

    // ---- loader: lrow 0..15 (+16i), chunk lq ----
    const int lrow = tid >> 3;
    const int lq   = tid & 7;
    const uint32_t dstoff = (uint32_t)(lrow * 128 + ((lq * 16) ^ ((lrow & 7) << 4)));
    const char* aglob = (const char*)(x + (size_t)(m0 + lrow) * KDIM + lq * 4);

    const char* bptr[7];
    uint32_t    bsz[7];
#pragma unroll
    for (int i = 0; i < 7; i++) {
        int bc = n0 + i * 16 + lrow;
        if (bc < NFC)        { bptr[i] = (const char*)(Wfc  + (size_t)bc * KDIM + lq * 4); bsz[i] = 16; }
        else if (bc < NCOLS) { bptr[i] = (const char*)(Wsel + (size_t)(bc - NFC) * KDIM + lq * 4); bsz[i] = 16; }
        else                 { bptr[i] = (const char*)Wfc; bsz[i] = 0; }
    }

    auto issue = [&](int kt) {
        int stage = kt & (STAGES - 1);
        uint32_t ad = bufs_u32 + stage * STAGE_BYTES + dstoff;
        uint32_t bd = ad + TILE_A;
        const char* as = aglob + (size_t)kt * 128;
#pragma unroll
        for (int i = 0; i < 8; i++)
            cp16(ad + i * 2048, as + (size_t)i * (16 * KDIM * 4), 16);
#pragma unroll
        for (int i = 0; i < 7; i++)
            cp16(bd + i * 2048, bptr[i] + (size_t)kt * 128, bsz[i]);
    };

    // ---- fragment constants ----
    const uint32_t aoff = (uint32_t)((warp * 32 + (lane & 15)) * 128);
    const uint32_t xS   = (uint32_t)((lane & 7) << 4);
    const uint32_t hA   = (lane & 16) ? 16u : 0u;
    const uint32_t boff = (uint32_t)(((lane & 7) + ((lane & 16) ? 8 : 0)) * 128);
    const uint32_t hB   = (lane & 8) ? 16u : 0u;

    float acc[2][14][4];
#pragma unroll
    for (int mi = 0; mi < 2; mi++)
#pragma unroll
        for (int nj = 0; nj < 14; nj++)
#pragma unroll
            for (int q = 0; q < 4; q++) acc[mi][nj][q] = 0.f;

    issue(0); cp_commit();
    issue(1); cp_commit();
    issue(2); cp_commit();

    uint32_t a[2][2][4], b[2][7][4];   // double-buffered fragments

#pragma unroll 1
    for (int kt = 0; kt < NKT; kt++) {
        cp_wait2();
        __syncthreads();
        if (kt + 3 < NKT) issue(kt + 3);
        cp_commit();

        const uint32_t As = bufs_u32 + (kt & (STAGES - 1)) * STAGE_BYTES;
        const uint32_t Bs = As + TILE_A;

        // preload + cvt ks=0 into buffer 0
        {
            const uint32_t ka = hA ^ xS;
            const uint32_t kb = hB ^ xS;
#pragma unroll
            for (int mi = 0; mi < 2; mi++) ldsm4(a[0][mi], As + aoff + mi * 2048 + ka);
#pragma unroll
            for (int p = 0; p < 7; p++)   ldsm4(b[0][p], Bs + boff + p * 2048 + kb);
#pragma unroll
            for (int mi = 0; mi < 2; mi++)
#pragma unroll
                for (int q = 0; q < 4; q++) a[0][mi][q] = f2tf(a[0][mi][q]);
#pragma unroll
            for (int p = 0; p < 7; p++)
#pragma unroll
                for (int q = 0; q < 4; q++) b[0][p][q] = f2tf(b[0][p][q]);
        }

#pragma unroll
        for (int ks = 0; ks < 4; ks++) {
            const int cur = ks & 1;
            const int nxt = cur ^ 1;
            // issue ldsm for ks+1 first: lands while the mma burst drains
            if (ks < 3) {
                const uint32_t ka = (uint32_t)((ks + 1) * 32 + hA) ^ xS;
                const uint32_t kb = (uint32_t)((ks + 1) * 32 + hB) ^ xS;
#pragma unroll
                for (int mi = 0; mi < 2; mi++) ldsm4(a[nxt][mi], As + aoff + mi * 2048 + ka);
#pragma unroll
                for (int p = 0; p < 7; p++)   ldsm4(b[nxt][p], Bs + boff + p * 2048 + kb);
            }
            // mma burst on current (28 HMMA)
#pragma unroll
            for (int mi = 0; mi < 2; mi++)
#pragma unroll
                for (int p = 0; p < 7; p++) {
                    mma8(acc[mi][2 * p],     a[cur][mi], &b[cur][p][0]);
                    mma8(acc[mi][2 * p + 1], a[cur][mi], &b[cur][p][2]);
                }
            // cvt next after the burst — ldsm results have landed by now
            if (ks < 3) {
#pragma unroll
                for (int mi = 0; mi < 2; mi++)
#pragma unroll
                    for (int q = 0; q < 4; q++) a[nxt][mi][q] = f2tf(a[nxt][mi][q]);
#pragma unroll
                for (int p = 0; p < 7; p++)
#pragma unroll
                    for (int q = 0; q < 4; q++) b[nxt][p][q] = f2tf(b[nxt][p][q]);
            }
        }
    }

    // ---- write U (guard pad columns) ----
    const int gid = lane >> 2;
    const int tig = lane & 3;
#pragma unroll
    for (int mi = 0; mi < 2; mi++) {
        int r0 = m0 + warp * 32 + mi * 16 + gid;
#pragma unroll
        for (int nj = 0; nj < 14; nj++) {
            int col = n0 + nj * 8 + 2 * tig;
            if (col < NCOLS) {
                *reinterpret_cast<float2*>(&g_U[(size_t)r0 * USTRIDE + col]) =
                    make_float2(acc[mi][nj][0], acc[mi][nj][1]);
                *reinterpret_cast<float2*>(&g_U[(size_t)(r0 + 8) * USTRIDE + col]) =
                    make_float2(acc[mi][nj][2], acc[mi][nj][3]);
            }
        }
    }
}

// ---------------------------------------------------------------------------
// epilogue (r5 version — fastest measured): float2, 1 row/block
// ---------------------------------------------------------------------------
__global__ void epi_kernel(const float* __restrict__ bsel, float* __restrict__ out) {
    int m = blockIdx.x;
    __shared__ float sx[10];
    if (threadIdx.x < 10)
        sx[threadIdx.x] = g_U[(size_t)m * USTRIDE + NFC + threadIdx.x] + bsel[threadIdx.x];
    __syncthreads();
    const float* Ur = g_U + (size_t)m * USTRIDE;
    float* orow = out + (size_t)m * 4096;
#pragma unroll 1
    for (int n = 0; n < 10; n++) {
        int base = n * NFC;                      // even
        float sxn = sx[n];
        int lim = (n == 9) ? (4096 - base) : NFC; // 410 or 406, both even
        const float* Gn = g_G + n * 416;
        for (int f = threadIdx.x * 2; f < lim; f += 512) {
            float2 u = *reinterpret_cast<const float2*>(Ur + f);
            float2 g = *reinterpret_cast<const float2*>(Gn + f);
            float2 cc = *reinterpret_cast<const float2*>(g_c + f);
            float2 r;
            r.x = fmaf(sxn, g.x, u.x + cc.x);
            r.y = fmaf(sxn, g.y, u.y + cc.y);
            *reinterpret_cast<float2*>(orow + base + f) = r;
        }
    }
}

// ---------------------------------------------------------------------------
extern "C" void kernel_launch(void* const* d_in, const int* in_sizes, int n_in,
                              void* d_out, int out_size) {
    const float* x    = (const float*)d_in[0];
    const float* Wsel = (const float*)d_in[1];
    const float* bsel = (const float*)d_in[2];
    const float* Wexp = (const float*)d_in[3];
    const float* bexp = (const float*)d_in[4];
    const float* Wfc  = (const float*)d_in[5];
    const float* bfc  = (const float*)d_in[6];
    float* out = (float*)d_out;

    int M = in_sizes[0] / KDIM;   // 4096

    const int smem_bytes = STAGES * STAGE_BYTES + 1024;   // 123904
    cudaFuncSetAttribute(gemm_kernel, cudaFuncAttributeMaxDynamicSharedMemorySize, smem_bytes);

    prep_part<<<dim3(NFC, KSPLIT), 128>>>(Wfc, Wexp, bexp);
    prep_combine<<<(PREPW + 255) / 256, 256>>>(bfc);
    dim3 grid(4, M / BM);   // 4 x 32 = 128 blocks
    gemm_kernel<<<grid, 128, smem_bytes>>>(x, Wfc, Wsel);
    epi_kernel<<<M, 256>>>(bsel, out);
}

// round 9
// speedup vs baseline: 1.4079x; 1.1240x over previous
#include <cuda_runtime.h>
#include <cstdint>

// ---------------------------------------------------------------------------
// y[m, n*410+f] = u[m,f] + sx[m,n]*G[n,f] + c[f]
//   U[:, 0:410] = X @ Wfc^T,  U[:, 410:420] = X @ Wsel^T  (one tf32 GEMM)
//   G = Wfc @ Wexp, c = Wfc @ bexp + bfc
// GEMM: r5/r7 shape (128 thr, 4 warps of 32x112, BN=112, cp.async 4-stage
// ring). B matrix pre-converted to tf32 (rna) in prep — g_Bt[448][4096]
// with zero pad rows — so the mainloop has NO B-side cvt (144->32 cvt/thr/kt)
// and no loader predicates. Bit-identical math to r7.
// ---------------------------------------------------------------------------

#define KDIM    4096
#define NFC     410
#define NCOLS   420
#define NBT     448
#define USTRIDE 432
#define MMAX    4096

#define BM 128
#define BN 112
#define BK 32
#define NKT (KDIM / BK)              // 128
#define STAGES 4
#define TILE_A  (BM * BK * 4)        // 16384
#define TILE_B  (BN * BK * 4)        // 14336
#define STAGE_BYTES (TILE_A + TILE_B) // 30720

#define KSPLIT 8
#define PREPW  4576

__device__ float g_U[MMAX * USTRIDE];
__device__ float g_G[10 * 416];
__device__ float g_c[416];
__device__ float g_part[KSPLIT][PREPW];
__device__ float g_Bt[NBT * KDIM];     // tf32-converted B (Wfc | Wsel | 0-pad)

// ---------------- helpers ----------------------------------------------------
__device__ __forceinline__ uint32_t smem_u32(const void* p) {
    uint32_t a;
    asm("{ .reg .u64 t; cvta.to.shared.u64 t, %1; cvt.u32.u64 %0, t; }" : "=r"(a) : "l"(p));
    return a;
}
__device__ __forceinline__ void cp16(uint32_t dst, const void* src) {
    asm volatile("cp.async.cg.shared.global [%0], [%1], 16;"
                 :: "r"(dst), "l"(src) : "memory");
}
__device__ __forceinline__ void cp_commit() {
    asm volatile("cp.async.commit_group;" ::: "memory");
}
__device__ __forceinline__ void cp_wait2() {
    asm volatile("cp.async.wait_group 2;" ::: "memory");
}
__device__ __forceinline__ void ldsm4(uint32_t* r, uint32_t a) {
    asm volatile("ldmatrix.sync.aligned.m8n8.x4.shared.b16 {%0,%1,%2,%3}, [%4];"
                 : "=r"(r[0]), "=r"(r[1]), "=r"(r[2]), "=r"(r[3]) : "r"(a));
}
__device__ __forceinline__ uint32_t f2tf(uint32_t v) {
    uint32_t r;
    asm("cvt.rna.tf32.f32 %0, %1;" : "=r"(r) : "f"(__uint_as_float(v)));
    return r;
}
__device__ __forceinline__ float f2tf_f(float v) {
    uint32_t r;
    asm("cvt.rna.tf32.f32 %0, %1;" : "=r"(r) : "f"(v));
    return __uint_as_float(r);
}
__device__ __forceinline__ void mma8(float* c, const uint32_t* a, const uint32_t* b) {
    asm volatile(
        "mma.sync.aligned.m16n8k8.row.col.f32.tf32.tf32.f32 "
        "{%0,%1,%2,%3}, {%4,%5,%6,%7}, {%8,%9}, {%0,%1,%2,%3};"
        : "+f"(c[0]), "+f"(c[1]), "+f"(c[2]), "+f"(c[3])
        : "r"(a[0]), "r"(a[1]), "r"(a[2]), "r"(a[3]), "r"(b[0]), "r"(b[1]));
}

// ---------------------------------------------------------------------------
// prep pass 1: G/c partials (f<410) + tf32 B materialization (all f<448)
// grid (448, 8), 128 threads
// ---------------------------------------------------------------------------
__global__ void prep_part(const float* __restrict__ Wfc, const float* __restrict__ Wsel,
                          const float* __restrict__ Wexp, const float* __restrict__ bexp) {
    int f  = blockIdx.x;                 // 0..447
    int kz = blockIdx.y;
    int k0 = kz * 512;
    const float* src = nullptr;
    if (f < NFC)        src = Wfc + (size_t)f * KDIM + k0;
    else if (f < NCOLS) src = Wsel + (size_t)(f - NFC) * KDIM + k0;

    float acc[11];
#pragma unroll
    for (int v = 0; v < 11; v++) acc[v] = 0.f;

#pragma unroll
    for (int it = 0; it < 4; it++) {
        int k = it * 128 + threadIdx.x;
        float w = src ? src[k] : 0.f;
        g_Bt[(size_t)f * KDIM + k0 + k] = f2tf_f(w);
        if (f < NFC) {
            const float* we = Wexp + (size_t)(k0 + k) * 10;
#pragma unroll
            for (int n = 0; n < 10; n++) acc[n] += w * we[n];
            acc[10] += w * bexp[k0 + k];
        }
    }
    if (f >= NFC) return;

    __shared__ float red[4][11];
    int lane = threadIdx.x & 31, warp = threadIdx.x >> 5;
#pragma unroll
    for (int v = 0; v < 11; v++) {
        float s = acc[v];
#pragma unroll
        for (int o = 16; o; o >>= 1) s += __shfl_xor_sync(0xffffffffu, s, o);
        if (lane == 0) red[warp][v] = s;
    }
    __syncthreads();
    if (threadIdx.x < 11) {
        float s = red[0][threadIdx.x] + red[1][threadIdx.x] +
                  red[2][threadIdx.x] + red[3][threadIdx.x];
        g_part[kz][threadIdx.x * 416 + f] = s;
    }
}

__global__ void prep_combine(const float* __restrict__ bfc) {
    int i = blockIdx.x * 256 + threadIdx.x;
    if (i >= PREPW) return;
    float s = 0.f;
#pragma unroll
    for (int kz = 0; kz < KSPLIT; kz++) s += g_part[kz][i];
    if (i < 10 * 416) {
        g_G[i] = s;
    } else {
        int f = i - 10 * 416;
        g_c[f] = (f < NFC) ? s + bfc[f] : s;
    }
}

// ---------------------------------------------------------------------------
// GEMM: 128x112 block, 4 warps (4wm x 1wn) of 32x112; B pre-converted
// ---------------------------------------------------------------------------
__global__ __launch_bounds__(128, 1)
void gemm_kernel(const float* __restrict__ x) {
    extern __shared__ char dyn[];
    char* bufs = (char*)(((uintptr_t)dyn + 1023) & ~(uintptr_t)1023);
    const uint32_t bufs_u32 = smem_u32(bufs);

    const int tid  = threadIdx.x;
    const int lane = tid & 31;
    const int warp = tid >> 5;         // wm 0..3, single wn
    const int m0   = blockIdx.y * BM;
    const int n0   = blockIdx.x * BN;

    // ---- loader: lrow 0..15 (+16i), chunk lq ----
    const int lrow = tid >> 3;
    const int lq   = tid & 7;
    const uint32_t dstoff = (uint32_t)(lrow * 128 + ((lq * 16) ^ ((lrow & 7) << 4)));
    const char* aglob = (const char*)(x + (size_t)(m0 + lrow) * KDIM + lq * 4);
    const char* bglob = (const char*)(g_Bt + (size_t)(n0 + lrow) * KDIM + lq * 4);

    auto issue = [&](int kt) {
        int stage = kt & (STAGES - 1);
        uint32_t ad = bufs_u32 + stage * STAGE_BYTES + dstoff;
        uint32_t bd = ad + TILE_A;
        const char* as = aglob + (size_t)kt * 128;
        const char* bs = bglob + (size_t)kt * 128;
#pragma unroll
        for (int i = 0; i < 8; i++)
            cp16(ad + i * 2048, as + (size_t)i * (16 * KDIM * 4));
#pragma unroll
        for (int i = 0; i < 7; i++)
            cp16(bd + i * 2048, bs + (size_t)i * (16 * KDIM * 4));
    };

    // ---- fragment constants ----
    const uint32_t aoff = (uint32_t)((warp * 32 + (lane & 15)) * 128);
    const uint32_t xS   = (uint32_t)((lane & 7) << 4);
    const uint32_t hA   = (lane & 16) ? 16u : 0u;
    const uint32_t boff = (uint32_t)(((lane & 7) + ((lane & 16) ? 8 : 0)) * 128);
    const uint32_t hB   = (lane & 8) ? 16u : 0u;

    float acc[2][14][4];
#pragma unroll
    for (int mi = 0; mi < 2; mi++)
#pragma unroll
        for (int nj = 0; nj < 14; nj++)
#pragma unroll
            for (int q = 0; q < 4; q++) acc[mi][nj][q] = 0.f;

    issue(0); cp_commit();
    issue(1); cp_commit();
    issue(2); cp_commit();

    uint32_t a[2][2][4], b[2][7][4];   // double-buffered fragments

#pragma unroll 1
    for (int kt = 0; kt < NKT; kt++) {
        cp_wait2();
        __syncthreads();
        if (kt + 3 < NKT) issue(kt + 3);
        cp_commit();

        const uint32_t As = bufs_u32 + (kt & (STAGES - 1)) * STAGE_BYTES;
        const uint32_t Bs = As + TILE_A;

        // preload ks=0
        {
            const uint32_t ka = hA ^ xS;
            const uint32_t kb = hB ^ xS;
#pragma unroll
            for (int mi = 0; mi < 2; mi++) ldsm4(a[0][mi], As + aoff + mi * 2048 + ka);
#pragma unroll
            for (int p = 0; p < 7; p++)   ldsm4(b[0][p], Bs + boff + p * 2048 + kb);
#pragma unroll
            for (int mi = 0; mi < 2; mi++)
#pragma unroll
                for (int q = 0; q < 4; q++) a[0][mi][q] = f2tf(a[0][mi][q]);
        }

#pragma unroll
        for (int ks = 0; ks < 4; ks++) {
            const int cur = ks & 1;
            const int nxt = cur ^ 1;
            if (ks < 3) {
                const uint32_t ka = (uint32_t)((ks + 1) * 32 + hA) ^ xS;
                const uint32_t kb = (uint32_t)((ks + 1) * 32 + hB) ^ xS;
#pragma unroll
                for (int mi = 0; mi < 2; mi++) ldsm4(a[nxt][mi], As + aoff + mi * 2048 + ka);
#pragma unroll
                for (int p = 0; p < 7; p++)   ldsm4(b[nxt][p], Bs + boff + p * 2048 + kb);
            }
#pragma unroll
            for (int mi = 0; mi < 2; mi++)
#pragma unroll
                for (int p = 0; p < 7; p++) {
                    mma8(acc[mi][2 * p],     a[cur][mi], &b[cur][p][0]);
                    mma8(acc[mi][2 * p + 1], a[cur][mi], &b[cur][p][2]);
                }
            if (ks < 3) {
#pragma unroll
                for (int mi = 0; mi < 2; mi++)
#pragma unroll
                    for (int q = 0; q < 4; q++) a[nxt][mi][q] = f2tf(a[nxt][mi][q]);
            }
        }
    }

    // ---- write U (guard pad columns) ----
    const int gid = lane >> 2;
    const int tig = lane & 3;
#pragma unroll
    for (int mi = 0; mi < 2; mi++) {
        int r0 = m0 + warp * 32 + mi * 16 + gid;
#pragma unroll
        for (int nj = 0; nj < 14; nj++) {
            int col = n0 + nj * 8 + 2 * tig;
            if (col < NCOLS) {
                *reinterpret_cast<float2*>(&g_U[(size_t)r0 * USTRIDE + col]) =
                    make_float2(acc[mi][nj][0], acc[mi][nj][1]);
                *reinterpret_cast<float2*>(&g_U[(size_t)(r0 + 8) * USTRIDE + col]) =
                    make_float2(acc[mi][nj][2], acc[mi][nj][3]);
            }
        }
    }
}

// ---------------------------------------------------------------------------
// epilogue (r5/r7 version): float2, 1 row/block
// ---------------------------------------------------------------------------
__global__ void epi_kernel(const float* __restrict__ bsel, float* __restrict__ out) {
    int m = blockIdx.x;
    __shared__ float sx[10];
    if (threadIdx.x < 10)
        sx[threadIdx.x] = g_U[(size_t)m * USTRIDE + NFC + threadIdx.x] + bsel[threadIdx.x];
    __syncthreads();
    const float* Ur = g_U + (size_t)m * USTRIDE;
    float* orow = out + (size_t)m * 4096;
#pragma unroll 1
    for (int n = 0; n < 10; n++) {
        int base = n * NFC;
        float sxn = sx[n];
        int lim = (n == 9) ? (4096 - base) : NFC;
        const float* Gn = g_G + n * 416;
        for (int f = threadIdx.x * 2; f < lim; f += 512) {
            float2 u = *reinterpret_cast<const float2*>(Ur + f);
            float2 g = *reinterpret_cast<const float2*>(Gn + f);
            float2 cc = *reinterpret_cast<const float2*>(g_c + f);
            float2 r;
            r.x = fmaf(sxn, g.x, u.x + cc.x);
            r.y = fmaf(sxn, g.y, u.y + cc.y);
            *reinterpret_cast<float2*>(orow + base + f) = r;
        }
    }
}

// ---------------------------------------------------------------------------
extern "C" void kernel_launch(void* const* d_in, const int* in_sizes, int n_in,
                              void* d_out, int out_size) {
    const float* x    = (const float*)d_in[0];
    const float* Wsel = (const float*)d_in[1];
    const float* bsel = (const float*)d_in[2];
    const float* Wexp = (const float*)d_in[3];
    const float* bexp = (const float*)d_in[4];
    const float* Wfc  = (const float*)d_in[5];
    const float* bfc  = (const float*)d_in[6];
    float* out = (float*)d_out;

    int M = in_sizes[0] / KDIM;   // 4096

    const int smem_bytes = STAGES * STAGE_BYTES + 1024;   // 123904
    cudaFuncSetAttribute(gemm_kernel, cudaFuncAttributeMaxDynamicSharedMemorySize, smem_bytes);

    prep_part<<<dim3(NBT, KSPLIT), 128>>>(Wfc, Wsel, Wexp, bexp);
    prep_combine<<<(PREPW + 255) / 256, 256>>>(bfc);
    dim3 grid(4, M / BM);   // 4 x 32 = 128 blocks
    gemm_kernel<<<grid, 128, smem_bytes>>>(x);
    epi_kernel<<<M, 256>>>(bsel, out);
}